// round 16
// baseline (speedup 1.0000x reference)
#include <cuda_runtime.h>
#include <cuda_bf16.h>
#include <math.h>

#define D     128
#define H     8
#define NMAX  50000
#define EMAX  800000
#define CAP   64     // max degree per bucket; P(Poisson(16) > 64) ~ 1e-18 per node

// ---------------- static device scratch ----------------
__device__ __nv_bfloat16 g_Qh[NMAX * D];
__device__ __nv_bfloat16 g_Kh[NMAX * D];
__device__ __nv_bfloat16 g_Vh[NMAX * D];
__device__ float g_h[NMAX * D];               // h = x + attn residual (fp32)
__device__ __nv_bfloat16 g_hnh[NMAX * D];     // LayerNorm(h) bf16
__device__ __nv_bfloat16 g_acth[NMAX * 2 * D];// gelu bf16
__device__ __nv_bfloat16 g_Wqt[D * D];        // Wq^T bf16 [128][128]
__device__ __nv_bfloat16 g_Wkt[D * D];
__device__ __nv_bfloat16 g_Wvt[D * D];
__device__ __nv_bfloat16 g_W1t[2 * D * D];    // W1^T bf16 [256][128]
__device__ __nv_bfloat16 g_W2t[2 * D * D];    // W2^T bf16 [128][256]
__device__ int g_cnt[NMAX];                   // zero at start; attn re-zeroes after use
__device__ int g_srt[NMAX * CAP];             // bucketed src ids per dst

// ---------------- single-kernel bucket sort ----------------
__global__ void k_bucket(const int* __restrict__ ei, int E) {
    int base = (blockIdx.x * blockDim.x + threadIdx.x) * 4;
    if (base + 3 < E) {
        int4 s4 = *(const int4*)(ei + base);
        int4 d4 = *(const int4*)(ei + E + base);
        int p0 = atomicAdd(&g_cnt[d4.x], 1);
        int p1 = atomicAdd(&g_cnt[d4.y], 1);
        int p2 = atomicAdd(&g_cnt[d4.z], 1);
        int p3 = atomicAdd(&g_cnt[d4.w], 1);
        if (p0 < CAP) g_srt[d4.x * CAP + p0] = s4.x;
        if (p1 < CAP) g_srt[d4.y * CAP + p1] = s4.y;
        if (p2 < CAP) g_srt[d4.z * CAP + p2] = s4.z;
        if (p3 < CAP) g_srt[d4.w * CAP + p3] = s4.w;
    } else {
        for (int e = base; e < E; ++e) {
            int src = __ldg(ei + e);
            int dst = __ldg(ei + E + e);
            int p = atomicAdd(&g_cnt[dst], 1);
            if (p < CAP) g_srt[dst * CAP + p] = src;
        }
    }
}

// ---------------- weight conversion ----------------
__global__ void k_convw(const float* __restrict__ Wq, const float* __restrict__ Wk,
                        const float* __restrict__ Wv, const float* __restrict__ W1,
                        const float* __restrict__ W2) {
    int i = blockIdx.x * blockDim.x + threadIdx.x;   // 0..32767
    if (i < 128 * 128) {
        int k = i >> 7, nn = i & 127;
        g_Wqt[nn * 128 + k] = __float2bfloat16(Wq[i]);
        g_Wkt[nn * 128 + k] = __float2bfloat16(Wk[i]);
        g_Wvt[nn * 128 + k] = __float2bfloat16(Wv[i]);
    }
    { int k = i >> 8, nn = i & 255; g_W1t[nn * 128 + k] = __float2bfloat16(W1[i]); }
    { int k = i >> 7, nn = i & 127; g_W2t[nn * 256 + k] = __float2bfloat16(W2[i]); }
}

// ---------------- mma / cp.async helpers ----------------
__device__ __forceinline__ void mma_bf16(float c[4],
    unsigned a0, unsigned a1, unsigned a2, unsigned a3,
    unsigned b0, unsigned b1)
{
    asm volatile(
        "mma.sync.aligned.m16n8k16.row.col.f32.bf16.bf16.f32 "
        "{%0,%1,%2,%3}, {%4,%5,%6,%7}, {%8,%9}, {%0,%1,%2,%3};"
        : "+f"(c[0]), "+f"(c[1]), "+f"(c[2]), "+f"(c[3])
        : "r"(a0), "r"(a1), "r"(a2), "r"(a3), "r"(b0), "r"(b1));
}

__device__ __forceinline__ void cpa16(void* smem_dst, const void* gsrc, int sz) {
    unsigned s = (unsigned)__cvta_generic_to_shared(smem_dst);
    asm volatile("cp.async.cg.shared.global [%0], [%1], 16, %2;"
                 :: "r"(s), "l"(gsrc), "r"(sz));
}

__device__ __forceinline__ unsigned pk(float a, float b) {
    __nv_bfloat162 h = __floats2bfloat162_rn(a, b);
    return *reinterpret_cast<unsigned*>(&h);
}

__device__ __forceinline__ float2 bf2f(unsigned u) {
    __nv_bfloat162 h = *reinterpret_cast<__nv_bfloat162*>(&u);
    return __bfloat1622float2(h);
}

#define SMEM_BF16_BYTES (2 * (2 * 128 * 40) * 2)

// ---------------- bf16 double-buffered GEMM body ----------------
// A: bf16 row-major (AF32=false) OR fp32 converted in-flight (AF32=true).
// Bt bf16 [ncols][KA] n-major.
// EPI: 1 = gelu(+bias)->bf16 ; 2 = +bias+R(fp32)->fp32 ; 3 = bf16 +bias
template <int KA, int EPI, bool AF32>
__device__ __forceinline__ void gemm_bf_body(
    const void* __restrict__ Av, const __nv_bfloat16* __restrict__ Bt,
    const float* __restrict__ bias, const float* __restrict__ R,
    void* __restrict__ Cv, int nrows, int ncols, int n0)
{
    extern __shared__ __nv_bfloat16 smh[];
#define SA(b, r, c) smh[(b) * (128 * 40) + (r) * 40 + (c)]
#define SB(b, r, c) smh[2 * 128 * 40 + (b) * (128 * 40) + (r) * 40 + (c)]

    const int tid  = threadIdx.x;
    const int m0   = blockIdx.x * 128;
    const int w    = tid >> 5;
    const int lane = tid & 31;
    const int g    = lane >> 2;
    const int tig  = lane & 3;
    const int wm   = (w >> 2) * 64;
    const int wn   = (w & 3) * 32;

    float acc[4][4][4];
#pragma unroll
    for (int i = 0; i < 4; ++i)
#pragma unroll
        for (int j = 0; j < 4; ++j)
#pragma unroll
            for (int q = 0; q < 4; ++q) acc[i][j][q] = 0.0f;

    auto load_tiles = [&](int buf, int kc) {
#pragma unroll
        for (int p = 0; p < 2; ++p) {
            int seg = tid + p * 256;
            int r = seg >> 2, ko = (seg & 3) << 3;
            if (AF32) {
                float4 a0 = make_float4(0.f, 0.f, 0.f, 0.f);
                float4 a1 = make_float4(0.f, 0.f, 0.f, 0.f);
                if (m0 + r < nrows) {
                    const float* src = (const float*)Av + (size_t)(m0 + r) * KA + kc + ko;
                    a0 = *(const float4*)src;
                    a1 = *(const float4*)(src + 4);
                }
                uint4 u = make_uint4(pk(a0.x, a0.y), pk(a0.z, a0.w),
                                     pk(a1.x, a1.y), pk(a1.z, a1.w));
                *(uint4*)&SA(buf, r, ko) = u;
            } else {
                int sz = (m0 + r < nrows) ? 16 : 0;
                cpa16(&SA(buf, r, ko),
                      (const __nv_bfloat16*)Av + (size_t)(m0 + r) * KA + kc + ko, sz);
            }
        }
#pragma unroll
        for (int p = 0; p < 2; ++p) {
            int seg = tid + p * 256;
            int r = seg >> 2, ko = (seg & 3) << 3;
            cpa16(&SB(buf, r, ko), Bt + (size_t)(n0 + r) * KA + kc + ko, 16);
        }
    };

    constexpr int NCH = KA / 32;
    load_tiles(0, 0);
    asm volatile("cp.async.commit_group;");

#pragma unroll 1
    for (int c = 0; c < NCH; ++c) {
        if (c + 1 < NCH) {
            load_tiles((c + 1) & 1, (c + 1) * 32);
            asm volatile("cp.async.commit_group;");
            asm volatile("cp.async.wait_group 1;");
        } else {
            asm volatile("cp.async.wait_group 0;");
        }
        __syncthreads();

        const int buf = c & 1;
#pragma unroll
        for (int ks = 0; ks < 2; ++ks) {
            const int kb = ks * 16 + 2 * tig;
            unsigned af[4][4];
#pragma unroll
            for (int ms = 0; ms < 4; ++ms) {
                int row = wm + ms * 16 + g;
                af[ms][0] = *(const unsigned*)&SA(buf, row,     kb);
                af[ms][1] = *(const unsigned*)&SA(buf, row + 8, kb);
                af[ms][2] = *(const unsigned*)&SA(buf, row,     kb + 8);
                af[ms][3] = *(const unsigned*)&SA(buf, row + 8, kb + 8);
            }
            unsigned bf[4][2];
#pragma unroll
            for (int ns = 0; ns < 4; ++ns) {
                int col = wn + ns * 8 + g;
                bf[ns][0] = *(const unsigned*)&SB(buf, col, kb);
                bf[ns][1] = *(const unsigned*)&SB(buf, col, kb + 8);
            }
#pragma unroll
            for (int ms = 0; ms < 4; ++ms)
#pragma unroll
                for (int ns = 0; ns < 4; ++ns)
                    mma_bf16(acc[ms][ns], af[ms][0], af[ms][1], af[ms][2], af[ms][3],
                             bf[ns][0], bf[ns][1]);
        }
        __syncthreads();
    }

#pragma unroll
    for (int ms = 0; ms < 4; ++ms) {
        int row0 = m0 + wm + ms * 16 + g;
#pragma unroll
        for (int half = 0; half < 2; ++half) {
            int row = row0 + half * 8;
            if (row >= nrows) continue;
#pragma unroll
            for (int ns = 0; ns < 4; ++ns) {
                int col = n0 + wn + ns * 8 + tig * 2;
                float v0 = acc[ms][ns][half * 2 + 0] + __ldg(bias + col);
                float v1 = acc[ms][ns][half * 2 + 1] + __ldg(bias + col + 1);
                if (EPI == 1) {
                    v0 = 0.5f * v0 * (1.0f + erff(v0 * 0.70710678118654752f));
                    v1 = 0.5f * v1 * (1.0f + erff(v1 * 0.70710678118654752f));
                    *(__nv_bfloat162*)((__nv_bfloat16*)Cv + (size_t)row * ncols + col) =
                        __floats2bfloat162_rn(v0, v1);
                } else if (EPI == 3) {
                    *(__nv_bfloat162*)((__nv_bfloat16*)Cv + (size_t)row * ncols + col) =
                        __floats2bfloat162_rn(v0, v1);
                } else {
                    const float2 r2 = *(const float2*)(R + (size_t)row * ncols + col);
                    *(float2*)((float*)Cv + (size_t)row * ncols + col) =
                        make_float2(v0 + r2.x, v1 + r2.y);
                }
            }
        }
    }
#undef SA
#undef SB
}

template <int KA, int EPI>
__global__ __launch_bounds__(256)
void k_gemm_bf(const __nv_bfloat16* __restrict__ A, const __nv_bfloat16* __restrict__ Bt,
               const float* __restrict__ bias, const float* __restrict__ R,
               void* __restrict__ Cv, int nrows, int ncols)
{
    gemm_bf_body<KA, EPI, false>(A, Bt, bias, R, Cv, nrows, ncols, blockIdx.y * 128);
}

__global__ __launch_bounds__(256)
void k_gemm_qkv_bf(const float* __restrict__ x,
                   const float* __restrict__ bq, const float* __restrict__ bk,
                   const float* __restrict__ bv, int nrows)
{
    if (blockIdx.z == 0)
        gemm_bf_body<128, 3, true>(x, g_Wqt, bq, nullptr, g_Qh, nrows, 128, 0);
    else if (blockIdx.z == 1)
        gemm_bf_body<128, 3, true>(x, g_Wkt, bk, nullptr, g_Kh, nrows, 128, 0);
    else
        gemm_bf_body<128, 3, true>(x, g_Wvt, bv, nullptr, g_Vh, nrows, 128, 0);
}

// ---------------- fused attention + residual + LayerNorm, warp per dst ----------------
// R14 layout (lane = 4 dims, quad = head), deepened to 8 edges per iteration
// (16 batched gathers, MLP 16) to cover the L2 gather latency.
__global__ __launch_bounds__(256)
void k_attn(const float* __restrict__ x,
            const float* __restrict__ lng, const float* __restrict__ lnb,
            int r0, int r1)
{
    int row = r0 + ((blockIdx.x * blockDim.x + threadIdx.x) >> 5);
    if (row >= r1) return;
    const int lane = threadIdx.x & 31;
    const size_t lo = (size_t)lane * 4;

    uint2 qr = *(const uint2*)(g_Qh + (size_t)row * D + lo);
    float2 qa = bf2f(qr.x), qb = bf2f(qr.y);
    const float qx = qa.x, qy = qa.y, qz = qb.x, qw = qb.y;
    float ax = 0.f, ay = 0.f, az = 0.f, aw = 0.f, den = 0.f;

    int cnt = g_cnt[row];
    if (cnt > CAP) cnt = CAP;
    const int* sp = g_srt + (size_t)row * CAP;
    int j = 0;

    // -------- 8-edge pipelined main loop --------
    for (; j + 7 < cnt; j += 8) {
        int4 sa = *(const int4*)(sp + j);
        int4 sb = *(const int4*)(sp + j + 4);
        // issue all 16 gathers up front (MLP 16)
        uint2 kr0 = *(const uint2*)(g_Kh + (size_t)sa.x * D + lo);
        uint2 kr1 = *(const uint2*)(g_Kh + (size_t)sa.y * D + lo);
        uint2 kr2 = *(const uint2*)(g_Kh + (size_t)sa.z * D + lo);
        uint2 kr3 = *(const uint2*)(g_Kh + (size_t)sa.w * D + lo);
        uint2 kr4 = *(const uint2*)(g_Kh + (size_t)sb.x * D + lo);
        uint2 kr5 = *(const uint2*)(g_Kh + (size_t)sb.y * D + lo);
        uint2 kr6 = *(const uint2*)(g_Kh + (size_t)sb.z * D + lo);
        uint2 kr7 = *(const uint2*)(g_Kh + (size_t)sb.w * D + lo);
        uint2 vr0 = *(const uint2*)(g_Vh + (size_t)sa.x * D + lo);
        uint2 vr1 = *(const uint2*)(g_Vh + (size_t)sa.y * D + lo);
        uint2 vr2 = *(const uint2*)(g_Vh + (size_t)sa.z * D + lo);
        uint2 vr3 = *(const uint2*)(g_Vh + (size_t)sa.w * D + lo);
        uint2 vr4 = *(const uint2*)(g_Vh + (size_t)sb.x * D + lo);
        uint2 vr5 = *(const uint2*)(g_Vh + (size_t)sb.y * D + lo);
        uint2 vr6 = *(const uint2*)(g_Vh + (size_t)sb.z * D + lo);
        uint2 vr7 = *(const uint2*)(g_Vh + (size_t)sb.w * D + lo);

        float2 k0a = bf2f(kr0.x), k0b = bf2f(kr0.y);
        float2 k1a = bf2f(kr1.x), k1b = bf2f(kr1.y);
        float2 k2a = bf2f(kr2.x), k2b = bf2f(kr2.y);
        float2 k3a = bf2f(kr3.x), k3b = bf2f(kr3.y);
        float2 k4a = bf2f(kr4.x), k4b = bf2f(kr4.y);
        float2 k5a = bf2f(kr5.x), k5b = bf2f(kr5.y);
        float2 k6a = bf2f(kr6.x), k6b = bf2f(kr6.y);
        float2 k7a = bf2f(kr7.x), k7b = bf2f(kr7.y);
        float d0 = qx * k0a.x + qy * k0a.y + qz * k0b.x + qw * k0b.y;
        float d1 = qx * k1a.x + qy * k1a.y + qz * k1b.x + qw * k1b.y;
        float d2 = qx * k2a.x + qy * k2a.y + qz * k2b.x + qw * k2b.y;
        float d3 = qx * k3a.x + qy * k3a.y + qz * k3b.x + qw * k3b.y;
        float d4 = qx * k4a.x + qy * k4a.y + qz * k4b.x + qw * k4b.y;
        float d5 = qx * k5a.x + qy * k5a.y + qz * k5b.x + qw * k5b.y;
        float d6 = qx * k6a.x + qy * k6a.y + qz * k6b.x + qw * k6b.y;
        float d7 = qx * k7a.x + qy * k7a.y + qz * k7b.x + qw * k7b.y;
        d0 += __shfl_xor_sync(~0u, d0, 1);
        d1 += __shfl_xor_sync(~0u, d1, 1);
        d2 += __shfl_xor_sync(~0u, d2, 1);
        d3 += __shfl_xor_sync(~0u, d3, 1);
        d4 += __shfl_xor_sync(~0u, d4, 1);
        d5 += __shfl_xor_sync(~0u, d5, 1);
        d6 += __shfl_xor_sync(~0u, d6, 1);
        d7 += __shfl_xor_sync(~0u, d7, 1);
        d0 += __shfl_xor_sync(~0u, d0, 2);
        d1 += __shfl_xor_sync(~0u, d1, 2);
        d2 += __shfl_xor_sync(~0u, d2, 2);
        d3 += __shfl_xor_sync(~0u, d3, 2);
        d4 += __shfl_xor_sync(~0u, d4, 2);
        d5 += __shfl_xor_sync(~0u, d5, 2);
        d6 += __shfl_xor_sync(~0u, d6, 2);
        d7 += __shfl_xor_sync(~0u, d7, 2);
        float e0 = __expf(d0 * 0.25f);
        float e1 = __expf(d1 * 0.25f);
        float e2 = __expf(d2 * 0.25f);
        float e3 = __expf(d3 * 0.25f);
        float e4 = __expf(d4 * 0.25f);
        float e5 = __expf(d5 * 0.25f);
        float e6 = __expf(d6 * 0.25f);
        float e7 = __expf(d7 * 0.25f);
        den += ((e0 + e1) + (e2 + e3)) + ((e4 + e5) + (e6 + e7));

        float2 v0a = bf2f(vr0.x), v0b = bf2f(vr0.y);
        float2 v1a = bf2f(vr1.x), v1b = bf2f(vr1.y);
        float2 v2a = bf2f(vr2.x), v2b = bf2f(vr2.y);
        float2 v3a = bf2f(vr3.x), v3b = bf2f(vr3.y);
        float2 v4a = bf2f(vr4.x), v4b = bf2f(vr4.y);
        float2 v5a = bf2f(vr5.x), v5b = bf2f(vr5.y);
        float2 v6a = bf2f(vr6.x), v6b = bf2f(vr6.y);
        float2 v7a = bf2f(vr7.x), v7b = bf2f(vr7.y);
        ax += (e0 * v0a.x + e1 * v1a.x + e2 * v2a.x + e3 * v3a.x)
            + (e4 * v4a.x + e5 * v5a.x + e6 * v6a.x + e7 * v7a.x);
        ay += (e0 * v0a.y + e1 * v1a.y + e2 * v2a.y + e3 * v3a.y)
            + (e4 * v4a.y + e5 * v5a.y + e6 * v6a.y + e7 * v7a.y);
        az += (e0 * v0b.x + e1 * v1b.x + e2 * v2b.x + e3 * v3b.x)
            + (e4 * v4b.x + e5 * v5b.x + e6 * v6b.x + e7 * v7b.x);
        aw += (e0 * v0b.y + e1 * v1b.y + e2 * v2b.y + e3 * v3b.y)
            + (e4 * v4b.y + e5 * v5b.y + e6 * v6b.y + e7 * v7b.y);
    }
    // -------- 4-edge tail --------
    for (; j + 3 < cnt; j += 4) {
        int4 s4 = *(const int4*)(sp + j);
        uint2 kr0 = *(const uint2*)(g_Kh + (size_t)s4.x * D + lo);
        uint2 kr1 = *(const uint2*)(g_Kh + (size_t)s4.y * D + lo);
        uint2 kr2 = *(const uint2*)(g_Kh + (size_t)s4.z * D + lo);
        uint2 kr3 = *(const uint2*)(g_Kh + (size_t)s4.w * D + lo);
        uint2 vr0 = *(const uint2*)(g_Vh + (size_t)s4.x * D + lo);
        uint2 vr1 = *(const uint2*)(g_Vh + (size_t)s4.y * D + lo);
        uint2 vr2 = *(const uint2*)(g_Vh + (size_t)s4.z * D + lo);
        uint2 vr3 = *(const uint2*)(g_Vh + (size_t)s4.w * D + lo);

        float2 k0a = bf2f(kr0.x), k0b = bf2f(kr0.y);
        float2 k1a = bf2f(kr1.x), k1b = bf2f(kr1.y);
        float2 k2a = bf2f(kr2.x), k2b = bf2f(kr2.y);
        float2 k3a = bf2f(kr3.x), k3b = bf2f(kr3.y);
        float d0 = qx * k0a.x + qy * k0a.y + qz * k0b.x + qw * k0b.y;
        float d1 = qx * k1a.x + qy * k1a.y + qz * k1b.x + qw * k1b.y;
        float d2 = qx * k2a.x + qy * k2a.y + qz * k2b.x + qw * k2b.y;
        float d3 = qx * k3a.x + qy * k3a.y + qz * k3b.x + qw * k3b.y;
        d0 += __shfl_xor_sync(~0u, d0, 1);
        d1 += __shfl_xor_sync(~0u, d1, 1);
        d2 += __shfl_xor_sync(~0u, d2, 1);
        d3 += __shfl_xor_sync(~0u, d3, 1);
        d0 += __shfl_xor_sync(~0u, d0, 2);
        d1 += __shfl_xor_sync(~0u, d1, 2);
        d2 += __shfl_xor_sync(~0u, d2, 2);
        d3 += __shfl_xor_sync(~0u, d3, 2);
        float e0 = __expf(d0 * 0.25f);
        float e1 = __expf(d1 * 0.25f);
        float e2 = __expf(d2 * 0.25f);
        float e3 = __expf(d3 * 0.25f);
        den += (e0 + e1) + (e2 + e3);
        float2 v0a = bf2f(vr0.x), v0b = bf2f(vr0.y);
        float2 v1a = bf2f(vr1.x), v1b = bf2f(vr1.y);
        float2 v2a = bf2f(vr2.x), v2b = bf2f(vr2.y);
        float2 v3a = bf2f(vr3.x), v3b = bf2f(vr3.y);
        ax += e0 * v0a.x + e1 * v1a.x + e2 * v2a.x + e3 * v3a.x;
        ay += e0 * v0a.y + e1 * v1a.y + e2 * v2a.y + e3 * v3a.y;
        az += e0 * v0b.x + e1 * v1b.x + e2 * v2b.x + e3 * v3b.x;
        aw += e0 * v0b.y + e1 * v1b.y + e2 * v2b.y + e3 * v3b.y;
    }
    // -------- scalar tail --------
    for (; j < cnt; ++j) {
        int s0 = sp[j];
        uint2 kr0 = *(const uint2*)(g_Kh + (size_t)s0 * D + lo);
        uint2 vr0 = *(const uint2*)(g_Vh + (size_t)s0 * D + lo);
        float2 ka = bf2f(kr0.x), kb = bf2f(kr0.y);
        float d0 = qx * ka.x + qy * ka.y + qz * kb.x + qw * kb.y;
        d0 += __shfl_xor_sync(~0u, d0, 1);
        d0 += __shfl_xor_sync(~0u, d0, 2);
        float e0 = __expf(d0 * 0.25f);
        den += e0;
        float2 va = bf2f(vr0.x), vb = bf2f(vr0.y);
        ax += e0 * va.x; ay += e0 * va.y;
        az += e0 * vb.x; aw += e0 * vb.y;
    }

    float inv = 1.0f / (den + 1e-16f);
    float4 xr = *(const float4*)(x + (size_t)row * D + lo);
    float4 hv = make_float4(xr.x + ax * inv, xr.y + ay * inv,
                            xr.z + az * inv, xr.w + aw * inv);
    *(float4*)(g_h + (size_t)row * D + lo) = hv;

    // fused LayerNorm -> bf16
    float s = hv.x + hv.y + hv.z + hv.w;
#pragma unroll
    for (int o = 16; o > 0; o >>= 1) s += __shfl_xor_sync(~0u, s, o);
    float mu = s * (1.0f / 128.0f);
    float dx = hv.x - mu, dy = hv.y - mu, dz = hv.z - mu, dw = hv.w - mu;
    float vs = dx * dx + dy * dy + dz * dz + dw * dw;
#pragma unroll
    for (int o = 16; o > 0; o >>= 1) vs += __shfl_xor_sync(~0u, vs, o);
    float r = rsqrtf(vs * (1.0f / 128.0f) + 1e-5f);
    float4 gg = *(const float4*)(lng + lo);
    float4 bb = *(const float4*)(lnb + lo);
    *(__nv_bfloat162*)(g_hnh + (size_t)row * D + lo) =
        __floats2bfloat162_rn(dx * r * gg.x + bb.x, dy * r * gg.y + bb.y);
    *(__nv_bfloat162*)(g_hnh + (size_t)row * D + lo + 2) =
        __floats2bfloat162_rn(dz * r * gg.z + bb.z, dw * r * gg.w + bb.w);

    // reset degree counter for the next graph replay
    if (lane == 0) g_cnt[row] = 0;
}

// ---------------- launch ----------------
extern "C" void kernel_launch(void* const* d_in, const int* in_sizes, int n_in,
                              void* d_out, int out_size) {
    const float* x    = (const float*)d_in[0];
    const int*   ei   = (const int*)  d_in[1];
    const float* Wq   = (const float*)d_in[2];
    const float* bq   = (const float*)d_in[3];
    const float* Wk   = (const float*)d_in[4];
    const float* bk   = (const float*)d_in[5];
    const float* Wv   = (const float*)d_in[6];
    const float* bv   = (const float*)d_in[7];
    const float* ln_g = (const float*)d_in[8];
    const float* ln_b = (const float*)d_in[9];
    const float* W1   = (const float*)d_in[10];
    const float* b1   = (const float*)d_in[11];
    const float* W2   = (const float*)d_in[12];
    const float* b2   = (const float*)d_in[13];
    float* out = (float*)d_out;

    const int n = in_sizes[0] / D;
    const int E = in_sizes[1] / 2;

    static bool inited = false;
    static __nv_bfloat16 *phn, *pact, *pW1t, *pW2t;
    static float *ph;
    static cudaStream_t s1, s2;
    static cudaEvent_t evFork, evSort, evW, evQKV, evC1;
    if (!inited) {
        cudaGetSymbolAddress((void**)&phn,  g_hnh);
        cudaGetSymbolAddress((void**)&pact, g_acth);
        cudaGetSymbolAddress((void**)&pW1t, g_W1t);
        cudaGetSymbolAddress((void**)&pW2t, g_W2t);
        cudaGetSymbolAddress((void**)&ph,   g_h);
        cudaStreamCreateWithFlags(&s1, cudaStreamNonBlocking);
        cudaStreamCreateWithFlags(&s2, cudaStreamNonBlocking);
        cudaEventCreateWithFlags(&evFork, cudaEventDisableTiming);
        cudaEventCreateWithFlags(&evSort, cudaEventDisableTiming);
        cudaEventCreateWithFlags(&evW,    cudaEventDisableTiming);
        cudaEventCreateWithFlags(&evQKV,  cudaEventDisableTiming);
        cudaEventCreateWithFlags(&evC1,   cudaEventDisableTiming);
        inited = true;
    }

    // fork side streams off the main (captured) stream
    cudaEventRecord(evFork, 0);
    cudaStreamWaitEvent(s1, evFork, 0);
    cudaStreamWaitEvent(s2, evFork, 0);

    // --- side stream 1: ONE-kernel bucket sort ---
    k_bucket<<<(E / 4 + 255) / 256, 256, 0, s1>>>(ei, E);
    cudaEventRecord(evSort, s1);

    // --- side stream 2: weights -> bf16 n-major ---
    k_convw<<<128, 256, 0, s2>>>(Wq, Wk, Wv, W1, W2);
    cudaEventRecord(evW, s2);

    // --- main: fused QKV (bf16 mma; x converted in-flight) ---
    cudaStreamWaitEvent(0, evW, 0);
    dim3 gq((n + 127) / 128, 1, 3);
    k_gemm_qkv_bf<<<gq, 256, SMEM_BF16_BYTES>>>(x, bq, bk, bv, n);
    cudaEventRecord(evQKV, 0);

    // --- chunked tail: chunk 0 on main, chunk 1 on s2 ---
    const int half = (((n + 1) / 2) + 127) & ~127;
    const int r1rows = n - half;

    cudaStreamWaitEvent(s2, evQKV, 0);
    cudaStreamWaitEvent(s2, evSort, 0);
    k_attn<<<(r1rows * 32 + 255) / 256, 256, 0, s2>>>(x, ln_g, ln_b, half, n);
    {
        dim3 gf1((r1rows + 127) / 128, 2);
        k_gemm_bf<128, 1><<<gf1, 256, SMEM_BF16_BYTES, s2>>>(
            phn + (size_t)half * D, pW1t, b1, nullptr,
            pact + (size_t)half * 2 * D, r1rows, 2 * D);
        dim3 gf2((r1rows + 127) / 128, 1);
        k_gemm_bf<256, 2><<<gf2, 256, SMEM_BF16_BYTES, s2>>>(
            pact + (size_t)half * 2 * D, pW2t, b2,
            ph + (size_t)half * D, out + (size_t)half * D, r1rows, D);
    }
    cudaEventRecord(evC1, s2);

    cudaStreamWaitEvent(0, evSort, 0);
    k_attn<<<(half * 32 + 255) / 256, 256>>>(x, ln_g, ln_b, 0, half);
    {
        dim3 gf1((half + 127) / 128, 2);
        k_gemm_bf<128, 1><<<gf1, 256, SMEM_BF16_BYTES>>>(
            phn, pW1t, b1, nullptr, pact, half, 2 * D);
        dim3 gf2((half + 127) / 128, 1);
        k_gemm_bf<256, 2><<<gf2, 256, SMEM_BF16_BYTES>>>(
            pact, pW2t, b2, ph, out, half, D);
    }

    cudaStreamWaitEvent(0, evC1, 0);
}

// round 17
// speedup vs baseline: 1.0393x; 1.0393x over previous
#include <cuda_runtime.h>
#include <cuda_bf16.h>
#include <math.h>

#define D     128
#define H     8
#define NMAX  50000
#define EMAX  800000
#define CAP   64     // max degree per bucket; P(Poisson(16) > 64) ~ 1e-18 per node

// ---------------- static device scratch ----------------
__device__ __nv_bfloat16 g_Qh[NMAX * D];
__device__ __nv_bfloat16 g_Kh[NMAX * D];
__device__ __nv_bfloat16 g_Vh[NMAX * D];
__device__ float g_h[NMAX * D];               // h = x + attn residual (fp32)
__device__ __nv_bfloat16 g_hnh[NMAX * D];     // LayerNorm(h) bf16
__device__ __nv_bfloat16 g_acth[NMAX * 2 * D];// gelu bf16
__device__ __nv_bfloat16 g_Wqt[D * D];        // Wq^T bf16 [128][128]
__device__ __nv_bfloat16 g_Wkt[D * D];
__device__ __nv_bfloat16 g_Wvt[D * D];
__device__ __nv_bfloat16 g_W1t[2 * D * D];    // W1^T bf16 [256][128]
__device__ __nv_bfloat16 g_W2t[2 * D * D];    // W2^T bf16 [128][256]
__device__ int g_cnt[NMAX];                   // zero at start; attn re-zeroes after use
__device__ int g_srt[NMAX * CAP];             // bucketed src ids per dst

// ---------------- single-kernel bucket sort ----------------
__global__ void k_bucket(const int* __restrict__ ei, int E) {
    int base = (blockIdx.x * blockDim.x + threadIdx.x) * 4;
    if (base + 3 < E) {
        int4 s4 = *(const int4*)(ei + base);
        int4 d4 = *(const int4*)(ei + E + base);
        int p0 = atomicAdd(&g_cnt[d4.x], 1);
        int p1 = atomicAdd(&g_cnt[d4.y], 1);
        int p2 = atomicAdd(&g_cnt[d4.z], 1);
        int p3 = atomicAdd(&g_cnt[d4.w], 1);
        if (p0 < CAP) g_srt[d4.x * CAP + p0] = s4.x;
        if (p1 < CAP) g_srt[d4.y * CAP + p1] = s4.y;
        if (p2 < CAP) g_srt[d4.z * CAP + p2] = s4.z;
        if (p3 < CAP) g_srt[d4.w * CAP + p3] = s4.w;
    } else {
        for (int e = base; e < E; ++e) {
            int src = __ldg(ei + e);
            int dst = __ldg(ei + E + e);
            int p = atomicAdd(&g_cnt[dst], 1);
            if (p < CAP) g_srt[dst * CAP + p] = src;
        }
    }
}

// ---------------- weight conversion ----------------
__global__ void k_convw(const float* __restrict__ Wq, const float* __restrict__ Wk,
                        const float* __restrict__ Wv, const float* __restrict__ W1,
                        const float* __restrict__ W2) {
    int i = blockIdx.x * blockDim.x + threadIdx.x;   // 0..32767
    if (i < 128 * 128) {
        int k = i >> 7, nn = i & 127;
        g_Wqt[nn * 128 + k] = __float2bfloat16(Wq[i]);
        g_Wkt[nn * 128 + k] = __float2bfloat16(Wk[i]);
        g_Wvt[nn * 128 + k] = __float2bfloat16(Wv[i]);
    }
    { int k = i >> 8, nn = i & 255; g_W1t[nn * 128 + k] = __float2bfloat16(W1[i]); }
    { int k = i >> 7, nn = i & 127; g_W2t[nn * 256 + k] = __float2bfloat16(W2[i]); }
}

// ---------------- mma / cp.async helpers ----------------
__device__ __forceinline__ void mma_bf16(float c[4],
    unsigned a0, unsigned a1, unsigned a2, unsigned a3,
    unsigned b0, unsigned b1)
{
    asm volatile(
        "mma.sync.aligned.m16n8k16.row.col.f32.bf16.bf16.f32 "
        "{%0,%1,%2,%3}, {%4,%5,%6,%7}, {%8,%9}, {%0,%1,%2,%3};"
        : "+f"(c[0]), "+f"(c[1]), "+f"(c[2]), "+f"(c[3])
        : "r"(a0), "r"(a1), "r"(a2), "r"(a3), "r"(b0), "r"(b1));
}

__device__ __forceinline__ void cpa16(void* smem_dst, const void* gsrc, int sz) {
    unsigned s = (unsigned)__cvta_generic_to_shared(smem_dst);
    asm volatile("cp.async.cg.shared.global [%0], [%1], 16, %2;"
                 :: "r"(s), "l"(gsrc), "r"(sz));
}

__device__ __forceinline__ unsigned pk(float a, float b) {
    __nv_bfloat162 h = __floats2bfloat162_rn(a, b);
    return *reinterpret_cast<unsigned*>(&h);
}

__device__ __forceinline__ float2 bf2f(unsigned u) {
    __nv_bfloat162 h = *reinterpret_cast<__nv_bfloat162*>(&u);
    return __bfloat1622float2(h);
}

// L1-bypassing 8-byte gather (L2-resident working set; L1 hit rate ~0)
__device__ __forceinline__ uint2 ldcg2(const __nv_bfloat16* p) {
    uint2 v;
    asm volatile("ld.global.cg.v2.u32 {%0, %1}, [%2];"
                 : "=r"(v.x), "=r"(v.y) : "l"(p));
    return v;
}

#define SMEM_BF16_BYTES (2 * (2 * 128 * 40) * 2)

// ---------------- bf16 double-buffered GEMM body ----------------
// A: bf16 row-major (AF32=false) OR fp32 converted in-flight (AF32=true).
// Bt bf16 [ncols][KA] n-major.
// EPI: 1 = gelu(+bias)->bf16 ; 2 = +bias+R(fp32)->fp32 ; 3 = bf16 +bias
template <int KA, int EPI, bool AF32>
__device__ __forceinline__ void gemm_bf_body(
    const void* __restrict__ Av, const __nv_bfloat16* __restrict__ Bt,
    const float* __restrict__ bias, const float* __restrict__ R,
    void* __restrict__ Cv, int nrows, int ncols, int n0)
{
    extern __shared__ __nv_bfloat16 smh[];
#define SA(b, r, c) smh[(b) * (128 * 40) + (r) * 40 + (c)]
#define SB(b, r, c) smh[2 * 128 * 40 + (b) * (128 * 40) + (r) * 40 + (c)]

    const int tid  = threadIdx.x;
    const int m0   = blockIdx.x * 128;
    const int w    = tid >> 5;
    const int lane = tid & 31;
    const int g    = lane >> 2;
    const int tig  = lane & 3;
    const int wm   = (w >> 2) * 64;
    const int wn   = (w & 3) * 32;

    float acc[4][4][4];
#pragma unroll
    for (int i = 0; i < 4; ++i)
#pragma unroll
        for (int j = 0; j < 4; ++j)
#pragma unroll
            for (int q = 0; q < 4; ++q) acc[i][j][q] = 0.0f;

    auto load_tiles = [&](int buf, int kc) {
#pragma unroll
        for (int p = 0; p < 2; ++p) {
            int seg = tid + p * 256;
            int r = seg >> 2, ko = (seg & 3) << 3;
            if (AF32) {
                float4 a0 = make_float4(0.f, 0.f, 0.f, 0.f);
                float4 a1 = make_float4(0.f, 0.f, 0.f, 0.f);
                if (m0 + r < nrows) {
                    const float* src = (const float*)Av + (size_t)(m0 + r) * KA + kc + ko;
                    a0 = *(const float4*)src;
                    a1 = *(const float4*)(src + 4);
                }
                uint4 u = make_uint4(pk(a0.x, a0.y), pk(a0.z, a0.w),
                                     pk(a1.x, a1.y), pk(a1.z, a1.w));
                *(uint4*)&SA(buf, r, ko) = u;
            } else {
                int sz = (m0 + r < nrows) ? 16 : 0;
                cpa16(&SA(buf, r, ko),
                      (const __nv_bfloat16*)Av + (size_t)(m0 + r) * KA + kc + ko, sz);
            }
        }
#pragma unroll
        for (int p = 0; p < 2; ++p) {
            int seg = tid + p * 256;
            int r = seg >> 2, ko = (seg & 3) << 3;
            cpa16(&SB(buf, r, ko), Bt + (size_t)(n0 + r) * KA + kc + ko, 16);
        }
    };

    constexpr int NCH = KA / 32;
    load_tiles(0, 0);
    asm volatile("cp.async.commit_group;");

#pragma unroll 1
    for (int c = 0; c < NCH; ++c) {
        if (c + 1 < NCH) {
            load_tiles((c + 1) & 1, (c + 1) * 32);
            asm volatile("cp.async.commit_group;");
            asm volatile("cp.async.wait_group 1;");
        } else {
            asm volatile("cp.async.wait_group 0;");
        }
        __syncthreads();

        const int buf = c & 1;
#pragma unroll
        for (int ks = 0; ks < 2; ++ks) {
            const int kb = ks * 16 + 2 * tig;
            unsigned af[4][4];
#pragma unroll
            for (int ms = 0; ms < 4; ++ms) {
                int row = wm + ms * 16 + g;
                af[ms][0] = *(const unsigned*)&SA(buf, row,     kb);
                af[ms][1] = *(const unsigned*)&SA(buf, row + 8, kb);
                af[ms][2] = *(const unsigned*)&SA(buf, row,     kb + 8);
                af[ms][3] = *(const unsigned*)&SA(buf, row + 8, kb + 8);
            }
            unsigned bf[4][2];
#pragma unroll
            for (int ns = 0; ns < 4; ++ns) {
                int col = wn + ns * 8 + g;
                bf[ns][0] = *(const unsigned*)&SB(buf, col, kb);
                bf[ns][1] = *(const unsigned*)&SB(buf, col, kb + 8);
            }
#pragma unroll
            for (int ms = 0; ms < 4; ++ms)
#pragma unroll
                for (int ns = 0; ns < 4; ++ns)
                    mma_bf16(acc[ms][ns], af[ms][0], af[ms][1], af[ms][2], af[ms][3],
                             bf[ns][0], bf[ns][1]);
        }
        __syncthreads();
    }

#pragma unroll
    for (int ms = 0; ms < 4; ++ms) {
        int row0 = m0 + wm + ms * 16 + g;
#pragma unroll
        for (int half = 0; half < 2; ++half) {
            int row = row0 + half * 8;
            if (row >= nrows) continue;
#pragma unroll
            for (int ns = 0; ns < 4; ++ns) {
                int col = n0 + wn + ns * 8 + tig * 2;
                float v0 = acc[ms][ns][half * 2 + 0] + __ldg(bias + col);
                float v1 = acc[ms][ns][half * 2 + 1] + __ldg(bias + col + 1);
                if (EPI == 1) {
                    v0 = 0.5f * v0 * (1.0f + erff(v0 * 0.70710678118654752f));
                    v1 = 0.5f * v1 * (1.0f + erff(v1 * 0.70710678118654752f));
                    *(__nv_bfloat162*)((__nv_bfloat16*)Cv + (size_t)row * ncols + col) =
                        __floats2bfloat162_rn(v0, v1);
                } else if (EPI == 3) {
                    *(__nv_bfloat162*)((__nv_bfloat16*)Cv + (size_t)row * ncols + col) =
                        __floats2bfloat162_rn(v0, v1);
                } else {
                    const float2 r2 = *(const float2*)(R + (size_t)row * ncols + col);
                    *(float2*)((float*)Cv + (size_t)row * ncols + col) =
                        make_float2(v0 + r2.x, v1 + r2.y);
                }
            }
        }
    }
#undef SA
#undef SB
}

template <int KA, int EPI>
__global__ __launch_bounds__(256)
void k_gemm_bf(const __nv_bfloat16* __restrict__ A, const __nv_bfloat16* __restrict__ Bt,
               const float* __restrict__ bias, const float* __restrict__ R,
               void* __restrict__ Cv, int nrows, int ncols)
{
    gemm_bf_body<KA, EPI, false>(A, Bt, bias, R, Cv, nrows, ncols, blockIdx.y * 128);
}

__global__ __launch_bounds__(256)
void k_gemm_qkv_bf(const float* __restrict__ x,
                   const float* __restrict__ bq, const float* __restrict__ bk,
                   const float* __restrict__ bv, int nrows)
{
    if (blockIdx.z == 0)
        gemm_bf_body<128, 3, true>(x, g_Wqt, bq, nullptr, g_Qh, nrows, 128, 0);
    else if (blockIdx.z == 1)
        gemm_bf_body<128, 3, true>(x, g_Wkt, bk, nullptr, g_Kh, nrows, 128, 0);
    else
        gemm_bf_body<128, 3, true>(x, g_Wvt, bv, nullptr, g_Vh, nrows, 128, 0);
}

// ---------------- fused attention + residual + LayerNorm, warp per dst ----------------
// R14 layout (lane = 4 dims, quad = head, 4 edges/iter) with L1-bypass gathers.
__global__ __launch_bounds__(256)
void k_attn(const float* __restrict__ x,
            const float* __restrict__ lng, const float* __restrict__ lnb,
            int r0, int r1)
{
    int row = r0 + ((blockIdx.x * blockDim.x + threadIdx.x) >> 5);
    if (row >= r1) return;
    const int lane = threadIdx.x & 31;
    const size_t lo = (size_t)lane * 4;

    uint2 qr = *(const uint2*)(g_Qh + (size_t)row * D + lo);
    float2 qa = bf2f(qr.x), qb = bf2f(qr.y);
    const float qx = qa.x, qy = qa.y, qz = qb.x, qw = qb.y;
    float ax = 0.f, ay = 0.f, az = 0.f, aw = 0.f, den = 0.f;

    int cnt = g_cnt[row];
    if (cnt > CAP) cnt = CAP;
    const int* sp = g_srt + (size_t)row * CAP;
    int j = 0;

    for (; j + 3 < cnt; j += 4) {
        int4 s4 = *(const int4*)(sp + j);
        uint2 kr0 = ldcg2(g_Kh + (size_t)s4.x * D + lo);
        uint2 kr1 = ldcg2(g_Kh + (size_t)s4.y * D + lo);
        uint2 kr2 = ldcg2(g_Kh + (size_t)s4.z * D + lo);
        uint2 kr3 = ldcg2(g_Kh + (size_t)s4.w * D + lo);
        uint2 vr0 = ldcg2(g_Vh + (size_t)s4.x * D + lo);
        uint2 vr1 = ldcg2(g_Vh + (size_t)s4.y * D + lo);
        uint2 vr2 = ldcg2(g_Vh + (size_t)s4.z * D + lo);
        uint2 vr3 = ldcg2(g_Vh + (size_t)s4.w * D + lo);

        float2 k0a = bf2f(kr0.x), k0b = bf2f(kr0.y);
        float2 k1a = bf2f(kr1.x), k1b = bf2f(kr1.y);
        float2 k2a = bf2f(kr2.x), k2b = bf2f(kr2.y);
        float2 k3a = bf2f(kr3.x), k3b = bf2f(kr3.y);
        float d0 = qx * k0a.x + qy * k0a.y + qz * k0b.x + qw * k0b.y;
        float d1 = qx * k1a.x + qy * k1a.y + qz * k1b.x + qw * k1b.y;
        float d2 = qx * k2a.x + qy * k2a.y + qz * k2b.x + qw * k2b.y;
        float d3 = qx * k3a.x + qy * k3a.y + qz * k3b.x + qw * k3b.y;
        d0 += __shfl_xor_sync(~0u, d0, 1);
        d1 += __shfl_xor_sync(~0u, d1, 1);
        d2 += __shfl_xor_sync(~0u, d2, 1);
        d3 += __shfl_xor_sync(~0u, d3, 1);
        d0 += __shfl_xor_sync(~0u, d0, 2);
        d1 += __shfl_xor_sync(~0u, d1, 2);
        d2 += __shfl_xor_sync(~0u, d2, 2);
        d3 += __shfl_xor_sync(~0u, d3, 2);
        float e0 = __expf(d0 * 0.25f);
        float e1 = __expf(d1 * 0.25f);
        float e2 = __expf(d2 * 0.25f);
        float e3 = __expf(d3 * 0.25f);
        den += (e0 + e1) + (e2 + e3);
        float2 v0a = bf2f(vr0.x), v0b = bf2f(vr0.y);
        float2 v1a = bf2f(vr1.x), v1b = bf2f(vr1.y);
        float2 v2a = bf2f(vr2.x), v2b = bf2f(vr2.y);
        float2 v3a = bf2f(vr3.x), v3b = bf2f(vr3.y);
        ax += e0 * v0a.x + e1 * v1a.x + e2 * v2a.x + e3 * v3a.x;
        ay += e0 * v0a.y + e1 * v1a.y + e2 * v2a.y + e3 * v3a.y;
        az += e0 * v0b.x + e1 * v1b.x + e2 * v2b.x + e3 * v3b.x;
        aw += e0 * v0b.y + e1 * v1b.y + e2 * v2b.y + e3 * v3b.y;
    }
    for (; j < cnt; ++j) {
        int s0 = sp[j];
        uint2 kr0 = ldcg2(g_Kh + (size_t)s0 * D + lo);
        uint2 vr0 = ldcg2(g_Vh + (size_t)s0 * D + lo);
        float2 ka = bf2f(kr0.x), kb = bf2f(kr0.y);
        float d0 = qx * ka.x + qy * ka.y + qz * kb.x + qw * kb.y;
        d0 += __shfl_xor_sync(~0u, d0, 1);
        d0 += __shfl_xor_sync(~0u, d0, 2);
        float e0 = __expf(d0 * 0.25f);
        den += e0;
        float2 va = bf2f(vr0.x), vb = bf2f(vr0.y);
        ax += e0 * va.x; ay += e0 * va.y;
        az += e0 * vb.x; aw += e0 * vb.y;
    }

    float inv = 1.0f / (den + 1e-16f);
    float4 xr = *(const float4*)(x + (size_t)row * D + lo);
    float4 hv = make_float4(xr.x + ax * inv, xr.y + ay * inv,
                            xr.z + az * inv, xr.w + aw * inv);
    *(float4*)(g_h + (size_t)row * D + lo) = hv;

    // fused LayerNorm -> bf16
    float s = hv.x + hv.y + hv.z + hv.w;
#pragma unroll
    for (int o = 16; o > 0; o >>= 1) s += __shfl_xor_sync(~0u, s, o);
    float mu = s * (1.0f / 128.0f);
    float dx = hv.x - mu, dy = hv.y - mu, dz = hv.z - mu, dw = hv.w - mu;
    float vs = dx * dx + dy * dy + dz * dz + dw * dw;
#pragma unroll
    for (int o = 16; o > 0; o >>= 1) vs += __shfl_xor_sync(~0u, vs, o);
    float r = rsqrtf(vs * (1.0f / 128.0f) + 1e-5f);
    float4 gg = *(const float4*)(lng + lo);
    float4 bb = *(const float4*)(lnb + lo);
    *(__nv_bfloat162*)(g_hnh + (size_t)row * D + lo) =
        __floats2bfloat162_rn(dx * r * gg.x + bb.x, dy * r * gg.y + bb.y);
    *(__nv_bfloat162*)(g_hnh + (size_t)row * D + lo + 2) =
        __floats2bfloat162_rn(dz * r * gg.z + bb.z, dw * r * gg.w + bb.w);

    // reset degree counter for the next graph replay
    if (lane == 0) g_cnt[row] = 0;
}

// ---------------- launch ----------------
extern "C" void kernel_launch(void* const* d_in, const int* in_sizes, int n_in,
                              void* d_out, int out_size) {
    const float* x    = (const float*)d_in[0];
    const int*   ei   = (const int*)  d_in[1];
    const float* Wq   = (const float*)d_in[2];
    const float* bq   = (const float*)d_in[3];
    const float* Wk   = (const float*)d_in[4];
    const float* bk   = (const float*)d_in[5];
    const float* Wv   = (const float*)d_in[6];
    const float* bv   = (const float*)d_in[7];
    const float* ln_g = (const float*)d_in[8];
    const float* ln_b = (const float*)d_in[9];
    const float* W1   = (const float*)d_in[10];
    const float* b1   = (const float*)d_in[11];
    const float* W2   = (const float*)d_in[12];
    const float* b2   = (const float*)d_in[13];
    float* out = (float*)d_out;

    const int n = in_sizes[0] / D;
    const int E = in_sizes[1] / 2;

    static bool inited = false;
    static __nv_bfloat16 *phn, *pact, *pW1t, *pW2t;
    static float *ph;
    static cudaStream_t s1, s2;
    static cudaEvent_t evFork, evSort, evW, evQKV, evC1;
    if (!inited) {
        cudaGetSymbolAddress((void**)&phn,  g_hnh);
        cudaGetSymbolAddress((void**)&pact, g_acth);
        cudaGetSymbolAddress((void**)&pW1t, g_W1t);
        cudaGetSymbolAddress((void**)&pW2t, g_W2t);
        cudaGetSymbolAddress((void**)&ph,   g_h);
        cudaStreamCreateWithFlags(&s1, cudaStreamNonBlocking);
        cudaStreamCreateWithFlags(&s2, cudaStreamNonBlocking);
        cudaEventCreateWithFlags(&evFork, cudaEventDisableTiming);
        cudaEventCreateWithFlags(&evSort, cudaEventDisableTiming);
        cudaEventCreateWithFlags(&evW,    cudaEventDisableTiming);
        cudaEventCreateWithFlags(&evQKV,  cudaEventDisableTiming);
        cudaEventCreateWithFlags(&evC1,   cudaEventDisableTiming);
        inited = true;
    }

    // fork side streams off the main (captured) stream
    cudaEventRecord(evFork, 0);
    cudaStreamWaitEvent(s1, evFork, 0);
    cudaStreamWaitEvent(s2, evFork, 0);

    // --- side stream 1: ONE-kernel bucket sort ---
    k_bucket<<<(E / 4 + 255) / 256, 256, 0, s1>>>(ei, E);
    cudaEventRecord(evSort, s1);

    // --- side stream 2: weights -> bf16 n-major ---
    k_convw<<<128, 256, 0, s2>>>(Wq, Wk, Wv, W1, W2);
    cudaEventRecord(evW, s2);

    // --- main: fused QKV (bf16 mma; x converted in-flight) ---
    cudaStreamWaitEvent(0, evW, 0);
    dim3 gq((n + 127) / 128, 1, 3);
    k_gemm_qkv_bf<<<gq, 256, SMEM_BF16_BYTES>>>(x, bq, bk, bv, n);
    cudaEventRecord(evQKV, 0);

    // --- chunked tail: chunk 0 on main, chunk 1 on s2 ---
    const int half = (((n + 1) / 2) + 127) & ~127;
    const int r1rows = n - half;

    cudaStreamWaitEvent(s2, evQKV, 0);
    cudaStreamWaitEvent(s2, evSort, 0);
    k_attn<<<(r1rows * 32 + 255) / 256, 256, 0, s2>>>(x, ln_g, ln_b, half, n);
    {
        dim3 gf1((r1rows + 127) / 128, 2);
        k_gemm_bf<128, 1><<<gf1, 256, SMEM_BF16_BYTES, s2>>>(
            phn + (size_t)half * D, pW1t, b1, nullptr,
            pact + (size_t)half * 2 * D, r1rows, 2 * D);
        dim3 gf2((r1rows + 127) / 128, 1);
        k_gemm_bf<256, 2><<<gf2, 256, SMEM_BF16_BYTES, s2>>>(
            pact + (size_t)half * 2 * D, pW2t, b2,
            ph + (size_t)half * D, out + (size_t)half * D, r1rows, D);
    }
    cudaEventRecord(evC1, s2);

    cudaStreamWaitEvent(0, evSort, 0);
    k_attn<<<(half * 32 + 255) / 256, 256>>>(x, ln_g, ln_b, 0, half);
    {
        dim3 gf1((half + 127) / 128, 2);
        k_gemm_bf<128, 1><<<gf1, 256, SMEM_BF16_BYTES>>>(
            phn, pW1t, b1, nullptr, pact, half, 2 * D);
        dim3 gf2((half + 127) / 128, 1);
        k_gemm_bf<256, 2><<<gf2, 256, SMEM_BF16_BYTES>>>(
            pact, pW2t, b2, ph, out, half, D);
    }

    cudaStreamWaitEvent(0, evC1, 0);
}